// round 14
// baseline (speedup 1.0000x reference)
#include <cuda_runtime.h>
#include <math.h>

// ANI AEV computer. M=32, A=48, S=4.
// Radial: 4 species x 16 ShfR = 64 ch. Angular: 10 sp-pairs x 4 ShfA x 8 ShfZ = 320 ch.
// Output (32, 48, 384) fp32.
//
// R7 (15.0): bucketed gather. R8 (14.0): Gaussian ladders. R9 (12.8): vec
// prologue. R11 (11.4 ncu): zeta hoisted to Phase A. R12 (11.6 ncu): 2-thr
// Phase A + closed-form decode (neutral).
// R13: Phase B unrolled by 2 with dual independent accumulators per slot --
//      breaks the blist->g8/pf2 dependent-LDS chain (~60 cyc/entry serial),
//      doubles LSU MLP. Everything else identical to R12.

#define MM 32
#define AA 48
#define SS 4
#define NSHFR 16
#define NSHFA 4
#define NSHFZ 8
#define RAD_SUB 16
#define ANG_SUB 32
#define NPAIRS_SP 10
#define NANG (NPAIRS_SP * ANG_SUB)                 // 320
#define OUT_PER_ATOM (SS * RAD_SUB + NANG)         // 384
#define RCR_F 5.2f
#define RCA_F 3.5f
#define NTHREADS 128
#define TILE 64                                    // pairs per tile (2 thr/pair)

__global__ __launch_bounds__(NTHREADS)
void aev_kernel(const float* __restrict__ coords,
                const float* __restrict__ EtaR,
                const float* __restrict__ ShfR,
                const float* __restrict__ EtaA,
                const float* __restrict__ Zeta,
                const float* __restrict__ ShfA,
                const float* __restrict__ ShfZ,
                const int*   __restrict__ species,
                float*       __restrict__ out)
{
    const int m   = blockIdx.x / AA;
    const int ci  = blockIdx.x % AA;
    const int tid = threadIdx.x;

    __shared__ float scrd[AA * 3];
    __shared__ int   ssp[AA];
    __shared__ float accR[SS * RAD_SUB];
    __shared__ float shfR[NSHFR], shfA_s[NSHFA];
    __shared__ float cz2[NSHFZ], sz2[NSHFZ];        // 0.5*cos(ShfZ), 0.5*sin(ShfZ)
    __shared__ int   ptab[SS * SS];
    __shared__ float s_etaR, s_etaA, s_zeta;
    __shared__ float s_invdR, s_2edR, s_2edA;
    __shared__ int   nnb;
    __shared__ float nbd[AA], nbx[AA], nby[AA], nbz[AA], nbfc[AA];
    __shared__ int   nbsp[AA];
    __shared__ float cuR[NSHFR - 1], cdR[NSHFR - 1], cauA[NSHFA - 1];
    // per-tile pair records + buckets
    __shared__ float g8[TILE][NSHFZ];               // zeta-powered angle terms
    __shared__ float pf2[TILE][NSHFA];              // radial-envelope terms
    __shared__ int   blist[NPAIRS_SP][TILE];
    __shared__ int   bcnt[NPAIRS_SP];

    // ---- SINGLE-SYNC prologue: everything built from global loads ----
    if (tid < 36)
        ((float4*)scrd)[tid] = ((const float4*)(coords + m * AA * 3))[tid];
    if (tid >= 40 && tid < 52)
        ((int4*)ssp)[tid - 40] = ((const int4*)(species + m * AA))[tid - 40];
    if (tid < NSHFR) shfR[tid] = ShfR[tid];
    if (tid < NSHFA) shfA_s[tid] = ShfA[tid];
    if (tid < NSHFZ) {
        float s = ShfZ[tid];                        // in [0.2, 3.0] -> fast path ok
        cz2[tid] = 0.5f * __cosf(s);
        sz2[tid] = 0.5f * __sinf(s);
    }
    if (tid < NSHFR - 1) {                          // radial ladder ratios
        const float k = EtaR[0] * (ShfR[1] - ShfR[0]);
        const float ss = ShfR[tid] + ShfR[tid + 1];
        cuR[tid] = __expf(-k * ss);
        cdR[tid] = __expf( k * ss);
    }
    if (tid >= 32 && tid < 32 + NSHFA - 1) {        // angular ladder ratios
        const int t = tid - 32;
        const float k = EtaA[0] * (ShfA[1] - ShfA[0]);
        cauA[t] = __expf(-k * (ShfA[t] + ShfA[t + 1]));
    }
    if (tid >= 96 && tid < 96 + SS * SS) {
        int t = tid - 96;
        int r = t / SS, c = t % SS;
        int lo = min(r, c), hi = max(r, c);
        ptab[t] = lo * SS - (lo * (lo - 1)) / 2 + (hi - lo);
    }
    if (tid == 64) {
        s_etaR = EtaR[0];
        s_etaA = EtaA[0];
        s_zeta = Zeta[0];
        const float dR = ShfR[1] - ShfR[0];
        s_invdR = 1.0f / dR;
        s_2edR  = 2.0f * EtaR[0] * dR;
        s_2edA  = 2.0f * EtaA[0] * (ShfA[1] - ShfA[0]);
        nnb = 0;
    }
    if (tid < SS * RAD_SUB) accR[tid] = 0.0f;
    if (tid >= 72 && tid < 72 + NPAIRS_SP) bcnt[tid - 72] = 0;
    __syncthreads();

    const float cxi = scrd[3 * ci + 0];
    const float cyi = scrd[3 * ci + 1];
    const float czi = scrd[3 * ci + 2];

    // ---- radial (Gaussian ladder, +-4) + neighbor list build ----
    if (tid < AA && tid != ci) {
        const int j = tid;
        const float dx = scrd[3 * j + 0] - cxi;
        const float dy = scrd[3 * j + 1] - cyi;
        const float dz = scrd[3 * j + 2] - czi;
        const float d2s = dx * dx + dy * dy + dz * dz;
        const float d   = d2s * rsqrtf(fmaxf(d2s, 1e-24f));

        if (d <= RCR_F) {
            const float fc   = 0.5f * __cosf(d * (float)(M_PI / 5.2)) + 0.5f;
            const float base = 0.25f * fc;
            const int   off  = ssp[j] * RAD_SUB;
            const float eR   = s_etaR;
            const float s0   = shfR[0];
            const float dR   = shfR[1] - s0;

            int ts = (int)floorf(fmaf(d - s0, s_invdR, 0.5f));
            ts = min(NSHFR - 1, max(0, ts));
            const float x = d - fmaf((float)ts, dR, s0);
            float f = base * __expf(-eR * x * x);
            atomicAdd(&accR[off + ts], f);

            const float R    = __expf(s_2edR * d);
            const float Rinv = __fdividef(1.0f, R);

            float fu = f;
            #pragma unroll
            for (int k = 1; k <= 4; k++) {
                const int t = ts + k;
                if (t > NSHFR - 1) break;
                fu *= R * cuR[t - 1];
                atomicAdd(&accR[off + t], fu);
            }
            float fd = f;
            #pragma unroll
            for (int k = 1; k <= 4; k++) {
                const int t = ts - k;
                if (t < 0) break;
                fd *= Rinv * cdR[t];
                atomicAdd(&accR[off + t], fd);
            }
        }
        if (d <= RCA_F) {
            const int slot = atomicAdd(&nnb, 1);
            nbd[slot]  = d;
            nbx[slot]  = dx;
            nby[slot]  = dy;
            nbz[slot]  = dz;
            nbfc[slot] = 1.41421356237f * (0.5f * __cosf(d * (float)(M_PI / 3.5)) + 0.5f);
            nbsp[slot] = ssp[j];
        }
    }
    __syncthreads();

    const int n     = nnb;
    const int npair = n * (n - 1) / 2;
    const int twon1 = 2 * n - 1;

    const float etaA = s_etaA;
    const float zeta = s_zeta;
    const bool  z32  = (zeta == 32.0f);

    // ---- channel ownership: iz/ia identical across a thread's 3 slots ----
    const int iz  = tid & 7;
    const int ia_ = (tid >> 3) & 3;
    const int px0 = tid >> 5;          // slot buckets: px0, px0+4, px0+8
    const bool has2 = (tid < NANG - 256);   // tid < 64

    // Phase-A role
    const int half = tid >> 6;          // 0 or 1
    const int pi   = tid & (TILE - 1);  // pair slot within tile

    float a0 = 0.0f, a1 = 0.0f, a2 = 0.0f;

    for (int base = 0; base < npair; base += TILE) {
        const int cnt = min(npair - base, TILE);

        // ---- Phase A: 2 threads per pair ----
        if (pi < cnt) {
            const int p = base + pi;
            // closed-form decode p -> (a, b), a < b
            const float disc = (float)(twon1 * twon1 - 8 * p);
            int a = (int)floorf(((float)twon1 - sqrtf(disc)) * 0.5f);
            int Sa = (a * (2 * n - a - 1)) >> 1;
            if (Sa > p)      { a--; Sa = (a * (2 * n - a - 1)) >> 1; }
            else { const int Sn = ((a + 1) * (2 * n - a - 2)) >> 1;
                   if (Sn <= p) { a++; Sa = Sn; } }
            const int b = a + 1 + (p - Sa);

            const float d1 = nbd[a], d2 = nbd[b];
            const float inv = __fdividef(1.0f, fmaxf(d1 * d2, 1e-16f));
            const float dot = nbx[a] * nbx[b] + nby[a] * nby[b] + nbz[a] * nbz[b];
            const float c   = 0.95f * dot * inv;
            const float omc = 1.0f - c * c;               // >= 0.0975
            const float sn  = omc * rsqrtf(omc);

            if (half == 0) {
                // f2 ladder (2 MUFU for 4 ShfA terms) + zeta[0..3] + push
                const float fcj2 = nbfc[a] * nbfc[b];      // = 2*fc1*fc2
                const float dm   = 0.5f * (d1 + d2);
                const float xa = dm - shfA_s[0];
                float f  = __expf(-etaA * xa * xa) * fcj2;
                const float RA = __expf(s_2edA * dm);
                float4 ff;
                ff.x = f;
                f *= RA * cauA[0]; ff.y = f;
                f *= RA * cauA[1]; ff.z = f;
                f *= RA * cauA[2]; ff.w = f;
                *(float4*)pf2[pi] = ff;

                float4 glo;
                #pragma unroll
                for (int z = 0; z < 4; z++) {
                    float t = fmaf(c, cz2[z], fmaf(sn, sz2[z], 0.5f));
                    if (z32) { t = t*t; t = t*t; t = t*t; t = t*t; t = t*t; }
                    else     { t = __powf(t, zeta); }
                    if (z == 0) glo.x = t; else if (z == 1) glo.y = t;
                    else if (z == 2) glo.z = t; else glo.w = t;
                }
                *(float4*)&g8[pi][0] = glo;

                const int pidx = ptab[nbsp[a] * SS + nbsp[b]];
                const int pos  = atomicAdd(&bcnt[pidx], 1);
                blist[pidx][pos] = pi;
            } else {
                float4 ghi;
                #pragma unroll
                for (int z = 4; z < 8; z++) {
                    float t = fmaf(c, cz2[z], fmaf(sn, sz2[z], 0.5f));
                    if (z32) { t = t*t; t = t*t; t = t*t; t = t*t; t = t*t; }
                    else     { t = __powf(t, zeta); }
                    if (z == 4) ghi.x = t; else if (z == 5) ghi.y = t;
                    else if (z == 6) ghi.z = t; else ghi.w = t;
                }
                *(float4*)&g8[pi][4] = ghi;
            }
        }
        __syncthreads();

        // ---- Phase B: unroll-by-2, dual accumulators per slot ----
        {
            const int c0n = bcnt[px0];
            float x0 = 0.0f, y0 = 0.0f;
            int e = 0;
            for (; e + 2 <= c0n; e += 2) {
                const int s0 = blist[px0][e];
                const int s1 = blist[px0][e + 1];
                x0 = fmaf(g8[s0][iz], pf2[s0][ia_], x0);
                y0 = fmaf(g8[s1][iz], pf2[s1][ia_], y0);
            }
            if (e < c0n) {
                const int s0 = blist[px0][e];
                x0 = fmaf(g8[s0][iz], pf2[s0][ia_], x0);
            }
            a0 += x0 + y0;

            const int c1n = bcnt[px0 + 4];
            float x1 = 0.0f, y1 = 0.0f;
            e = 0;
            for (; e + 2 <= c1n; e += 2) {
                const int s0 = blist[px0 + 4][e];
                const int s1 = blist[px0 + 4][e + 1];
                x1 = fmaf(g8[s0][iz], pf2[s0][ia_], x1);
                y1 = fmaf(g8[s1][iz], pf2[s1][ia_], y1);
            }
            if (e < c1n) {
                const int s0 = blist[px0 + 4][e];
                x1 = fmaf(g8[s0][iz], pf2[s0][ia_], x1);
            }
            a1 += x1 + y1;

            if (has2) {
                const int c2n = bcnt[px0 + 8];
                float x2 = 0.0f, y2 = 0.0f;
                e = 0;
                for (; e + 2 <= c2n; e += 2) {
                    const int s0 = blist[px0 + 8][e];
                    const int s1 = blist[px0 + 8][e + 1];
                    x2 = fmaf(g8[s0][iz], pf2[s0][ia_], x2);
                    y2 = fmaf(g8[s1][iz], pf2[s1][ia_], y2);
                }
                if (e < c2n) {
                    const int s0 = blist[px0 + 8][e];
                    x2 = fmaf(g8[s0][iz], pf2[s0][ia_], x2);
                }
                a2 += x2 + y2;
            }
        }
        // only pay barriers/reset if another tile follows
        if (base + TILE < npair) {
            __syncthreads();
            if (tid < NPAIRS_SP) bcnt[tid] = 0;
            __syncthreads();
        }
    }

    // ---- write out ----
    float* o = out + (size_t)(m * AA + ci) * OUT_PER_ATOM;
    if (tid < SS * RAD_SUB) o[tid] = accR[tid];
    o[SS * RAD_SUB + tid]       = a0;
    o[SS * RAD_SUB + tid + 128] = a1;
    if (has2) o[SS * RAD_SUB + tid + 256] = a2;
}

extern "C" void kernel_launch(void* const* d_in, const int* in_sizes, int n_in,
                              void* d_out, int out_size)
{
    const float* coords  = (const float*)d_in[0];
    const float* EtaR    = (const float*)d_in[1];
    const float* ShfR    = (const float*)d_in[2];
    const float* EtaA    = (const float*)d_in[3];
    const float* Zeta    = (const float*)d_in[4];
    const float* ShfA    = (const float*)d_in[5];
    const float* ShfZ    = (const float*)d_in[6];
    const int*   species = (const int*)d_in[7];
    float* out = (float*)d_out;

    aev_kernel<<<MM * AA, NTHREADS>>>(coords, EtaR, ShfR, EtaA, Zeta,
                                      ShfA, ShfZ, species, out);
}

// round 15
// speedup vs baseline: 1.0226x; 1.0226x over previous
#include <cuda_runtime.h>
#include <math.h>

// ANI AEV computer. M=32, A=48, S=4.
// Radial: 4 species x 16 ShfR = 64 ch. Angular: 10 sp-pairs x 4 ShfA x 8 ShfZ = 320 ch.
// Output (32, 48, 384) fp32.
//
// R7 (15.0): bucketed gather. R8 (14.0): Gaussian ladders. R9 (12.8): vec
// prologue. R11-R13 (~11.5 ncu): zeta hoisted to Phase A; micro-variants neutral.
// R14: warp-specialized overlap -- distance pass stores sd[]; then radial
//      ladder (warps 0-1, SMSP 0/1) runs CONCURRENTLY with angular Phase A
//      (warps 2-3, SMSP 2/3, 1 thread/pair). Disjoint MUFU units. Same
//      barrier count. npair>64 handled by a rare serial tile loop.

#define MM 32
#define AA 48
#define SS 4
#define NSHFR 16
#define NSHFA 4
#define NSHFZ 8
#define RAD_SUB 16
#define ANG_SUB 32
#define NPAIRS_SP 10
#define NANG (NPAIRS_SP * ANG_SUB)                 // 320
#define OUT_PER_ATOM (SS * RAD_SUB + NANG)         // 384
#define RCR_F 5.2f
#define RCA_F 3.5f
#define NTHREADS 128
#define TILE 64                                    // pairs per tile

__global__ __launch_bounds__(NTHREADS)
void aev_kernel(const float* __restrict__ coords,
                const float* __restrict__ EtaR,
                const float* __restrict__ ShfR,
                const float* __restrict__ EtaA,
                const float* __restrict__ Zeta,
                const float* __restrict__ ShfA,
                const float* __restrict__ ShfZ,
                const int*   __restrict__ species,
                float*       __restrict__ out)
{
    const int m   = blockIdx.x / AA;
    const int ci  = blockIdx.x % AA;
    const int tid = threadIdx.x;

    __shared__ float scrd[AA * 3];
    __shared__ int   ssp[AA];
    __shared__ float accR[SS * RAD_SUB];
    __shared__ float shfR[NSHFR], shfA_s[NSHFA];
    __shared__ float cz2[NSHFZ], sz2[NSHFZ];        // 0.5*cos(ShfZ), 0.5*sin(ShfZ)
    __shared__ int   ptab[SS * SS];
    __shared__ float s_etaR, s_etaA, s_zeta;
    __shared__ float s_invdR, s_2edR, s_2edA;
    __shared__ int   nnb;
    __shared__ float sd[AA];                        // all distances (for radial)
    __shared__ float nbd[AA], nbx[AA], nby[AA], nbz[AA], nbfc[AA];
    __shared__ int   nbsp[AA];
    __shared__ float cuR[NSHFR - 1], cdR[NSHFR - 1], cauA[NSHFA - 1];
    // per-tile pair records + buckets
    __shared__ float g8[TILE][NSHFZ];               // zeta-powered angle terms
    __shared__ float pf2[TILE][NSHFA];              // radial-envelope terms
    __shared__ int   blist[NPAIRS_SP][TILE];
    __shared__ int   bcnt[NPAIRS_SP];

    // ---- SINGLE-SYNC prologue: everything built from global loads ----
    if (tid < 36)
        ((float4*)scrd)[tid] = ((const float4*)(coords + m * AA * 3))[tid];
    if (tid >= 40 && tid < 52)
        ((int4*)ssp)[tid - 40] = ((const int4*)(species + m * AA))[tid - 40];
    if (tid < NSHFR) shfR[tid] = ShfR[tid];
    if (tid < NSHFA) shfA_s[tid] = ShfA[tid];
    if (tid < NSHFZ) {
        float s = ShfZ[tid];                        // in [0.2, 3.0] -> fast path ok
        cz2[tid] = 0.5f * __cosf(s);
        sz2[tid] = 0.5f * __sinf(s);
    }
    if (tid < NSHFR - 1) {                          // radial ladder ratios
        const float k = EtaR[0] * (ShfR[1] - ShfR[0]);
        const float ss = ShfR[tid] + ShfR[tid + 1];
        cuR[tid] = __expf(-k * ss);
        cdR[tid] = __expf( k * ss);
    }
    if (tid >= 32 && tid < 32 + NSHFA - 1) {        // angular ladder ratios
        const int t = tid - 32;
        const float k = EtaA[0] * (ShfA[1] - ShfA[0]);
        cauA[t] = __expf(-k * (ShfA[t] + ShfA[t + 1]));
    }
    if (tid >= 96 && tid < 96 + SS * SS) {
        int t = tid - 96;
        int r = t / SS, c = t % SS;
        int lo = min(r, c), hi = max(r, c);
        ptab[t] = lo * SS - (lo * (lo - 1)) / 2 + (hi - lo);
    }
    if (tid == 64) {
        s_etaR = EtaR[0];
        s_etaA = EtaA[0];
        s_zeta = Zeta[0];
        const float dR = ShfR[1] - ShfR[0];
        s_invdR = 1.0f / dR;
        s_2edR  = 2.0f * EtaR[0] * dR;
        s_2edA  = 2.0f * EtaA[0] * (ShfA[1] - ShfA[0]);
        nnb = 0;
    }
    if (tid < SS * RAD_SUB) accR[tid] = 0.0f;
    if (tid >= 72 && tid < 72 + NPAIRS_SP) bcnt[tid - 72] = 0;
    __syncthreads();

    const float cxi = scrd[3 * ci + 0];
    const float cyi = scrd[3 * ci + 1];
    const float czi = scrd[3 * ci + 2];

    // ---- distance pass: store sd[] + build RCA neighbor list ----
    if (tid < AA && tid != ci) {
        const int j = tid;
        const float dx = scrd[3 * j + 0] - cxi;
        const float dy = scrd[3 * j + 1] - cyi;
        const float dz = scrd[3 * j + 2] - czi;
        const float d2s = dx * dx + dy * dy + dz * dz;
        const float d   = d2s * rsqrtf(fmaxf(d2s, 1e-24f));
        sd[j] = d;
        if (d <= RCA_F) {
            const int slot = atomicAdd(&nnb, 1);
            nbd[slot]  = d;
            nbx[slot]  = dx;
            nby[slot]  = dy;
            nbz[slot]  = dz;
            nbfc[slot] = 1.41421356237f * (0.5f * __cosf(d * (float)(M_PI / 3.5)) + 0.5f);
            nbsp[slot] = ssp[j];
        }
    }
    __syncthreads();

    const int n     = nnb;
    const int npair = n * (n - 1) / 2;
    const int twon1 = 2 * n - 1;

    const float etaA = s_etaA;
    const float zeta = s_zeta;
    const bool  z32  = (zeta == 32.0f);

    // Phase A for one pair P into record slot SLOT (full 8-z, 1 thread).
    #define PHASE_A(P, SLOT) do {                                              \
        const int p_ = (P);                                                    \
        const float disc = (float)(twon1 * twon1 - 8 * p_);                    \
        int a = (int)floorf(((float)twon1 - sqrtf(disc)) * 0.5f);              \
        int Sa = (a * (2 * n - a - 1)) >> 1;                                   \
        if (Sa > p_)      { a--; Sa = (a * (2 * n - a - 1)) >> 1; }            \
        else { const int Sn = ((a + 1) * (2 * n - a - 2)) >> 1;                \
               if (Sn <= p_) { a++; Sa = Sn; } }                               \
        const int b = a + 1 + (p_ - Sa);                                       \
        const float d1 = nbd[a], d2 = nbd[b];                                  \
        const float inv = __fdividef(1.0f, fmaxf(d1 * d2, 1e-16f));            \
        const float dot = nbx[a] * nbx[b] + nby[a] * nby[b] + nbz[a] * nbz[b]; \
        const float c   = 0.95f * dot * inv;                                   \
        const float omc = 1.0f - c * c;                                        \
        const float sn  = omc * rsqrtf(omc);                                   \
        const float fcj2 = nbfc[a] * nbfc[b];                                  \
        const float dm   = 0.5f * (d1 + d2);                                   \
        const float xa = dm - shfA_s[0];                                       \
        float f  = __expf(-etaA * xa * xa) * fcj2;                             \
        const float RA = __expf(s_2edA * dm);                                  \
        float4 ff;                                                             \
        ff.x = f;                                                              \
        f *= RA * cauA[0]; ff.y = f;                                           \
        f *= RA * cauA[1]; ff.z = f;                                           \
        f *= RA * cauA[2]; ff.w = f;                                           \
        *(float4*)pf2[SLOT] = ff;                                              \
        float4 glo, ghi;                                                       \
        _Pragma("unroll")                                                      \
        for (int z = 0; z < NSHFZ; z++) {                                      \
            float t = fmaf(c, cz2[z], fmaf(sn, sz2[z], 0.5f));                 \
            if (z32) { t = t*t; t = t*t; t = t*t; t = t*t; t = t*t; }          \
            else     { t = __powf(t, zeta); }                                  \
            if (z == 0) glo.x = t; else if (z == 1) glo.y = t;                 \
            else if (z == 2) glo.z = t; else if (z == 3) glo.w = t;            \
            else if (z == 4) ghi.x = t; else if (z == 5) ghi.y = t;            \
            else if (z == 6) ghi.z = t; else ghi.w = t;                        \
        }                                                                      \
        *(float4*)&g8[SLOT][0] = glo;                                          \
        *(float4*)&g8[SLOT][4] = ghi;                                          \
        const int pidx = ptab[nbsp[a] * SS + nbsp[b]];                         \
        const int pos  = atomicAdd(&bcnt[pidx], 1);                            \
        blist[pidx][pos] = SLOT;                                               \
    } while (0)

    // ---- channel ownership: iz/ia identical across a thread's 3 slots ----
    const int iz  = tid & 7;
    const int ia_ = (tid >> 3) & 3;
    const int px0 = tid >> 5;          // slot buckets: px0, px0+4, px0+8
    const bool has2 = (tid < NANG - 256);   // tid < 64

    float a0 = 0.0f, a1 = 0.0f, a2 = 0.0f;

    for (int base = 0; ; base += TILE) {
        const int cnt = min(npair - base, TILE);

        if (base == 0) {
            // ---- OVERLAPPED: warps 0-1 radial ladder, warps 2-3 Phase A ----
            if (tid < AA && tid != ci) {
                const float d = sd[tid];
                if (d <= RCR_F) {
                    const float fc   = 0.5f * __cosf(d * (float)(M_PI / 5.2)) + 0.5f;
                    const float base_ = 0.25f * fc;
                    const int   off  = ssp[tid] * RAD_SUB;
                    const float eR   = s_etaR;
                    const float s0   = shfR[0];
                    const float dR   = shfR[1] - s0;

                    int ts = (int)floorf(fmaf(d - s0, s_invdR, 0.5f));
                    ts = min(NSHFR - 1, max(0, ts));
                    const float x = d - fmaf((float)ts, dR, s0);
                    float f = base_ * __expf(-eR * x * x);
                    atomicAdd(&accR[off + ts], f);

                    const float R    = __expf(s_2edR * d);
                    const float Rinv = __fdividef(1.0f, R);

                    float fu = f;
                    #pragma unroll
                    for (int k = 1; k <= 4; k++) {
                        const int t = ts + k;
                        if (t > NSHFR - 1) break;
                        fu *= R * cuR[t - 1];
                        atomicAdd(&accR[off + t], fu);
                    }
                    float fd = f;
                    #pragma unroll
                    for (int k = 1; k <= 4; k++) {
                        const int t = ts - k;
                        if (t < 0) break;
                        fd *= Rinv * cdR[t];
                        atomicAdd(&accR[off + t], fd);
                    }
                }
            } else if (tid >= TILE) {
                const int slot = tid - TILE;
                if (slot < cnt) PHASE_A(slot, slot);
            }
        } else {
            // rare path: npair > 64
            __syncthreads();
            if (tid < NPAIRS_SP) bcnt[tid] = 0;
            __syncthreads();
            if (tid >= TILE) {
                const int slot = tid - TILE;
                if (slot < cnt) PHASE_A(base + slot, slot);
            }
        }
        __syncthreads();

        // ---- Phase B: gather (2 broadcast LDS + 1 FMA per bucket entry) ----
        {
            const int c0n = bcnt[px0];
            for (int e = 0; e < c0n; e++) {
                const int s = blist[px0][e];
                a0 = fmaf(g8[s][iz], pf2[s][ia_], a0);
            }
            const int c1n = bcnt[px0 + 4];
            for (int e = 0; e < c1n; e++) {
                const int s = blist[px0 + 4][e];
                a1 = fmaf(g8[s][iz], pf2[s][ia_], a1);
            }
            if (has2) {
                const int c2n = bcnt[px0 + 8];
                for (int e = 0; e < c2n; e++) {
                    const int s = blist[px0 + 8][e];
                    a2 = fmaf(g8[s][iz], pf2[s][ia_], a2);
                }
            }
        }
        if (base + TILE >= npair) break;
    }

    // ---- write out ----
    float* o = out + (size_t)(m * AA + ci) * OUT_PER_ATOM;
    if (tid < SS * RAD_SUB) o[tid] = accR[tid];
    o[SS * RAD_SUB + tid]       = a0;
    o[SS * RAD_SUB + tid + 128] = a1;
    if (has2) o[SS * RAD_SUB + tid + 256] = a2;
}

extern "C" void kernel_launch(void* const* d_in, const int* in_sizes, int n_in,
                              void* d_out, int out_size)
{
    const float* coords  = (const float*)d_in[0];
    const float* EtaR    = (const float*)d_in[1];
    const float* ShfR    = (const float*)d_in[2];
    const float* EtaA    = (const float*)d_in[3];
    const float* Zeta    = (const float*)d_in[4];
    const float* ShfA    = (const float*)d_in[5];
    const float* ShfZ    = (const float*)d_in[6];
    const int*   species = (const int*)d_in[7];
    float* out = (float*)d_out;

    aev_kernel<<<MM * AA, NTHREADS>>>(coords, EtaR, ShfR, EtaA, Zeta,
                                      ShfA, ShfZ, species, out);
}